// round 9
// baseline (speedup 1.0000x reference)
#include <cuda_runtime.h>
#include <cuda_pipeline_primitives.h>
#include <math.h>

#define T_STEPS 1024
#define K_FEAT  512
#define BLOCK   32            // single-warp CTAs
#define CHUNK   16            // time steps per cp.async commit group
#define NGROUPS 8             // groups in flight -> 128 stages = 16KB/warp
#define NCHUNKS (T_STEPS / CHUNK)   // 64

// One warp owns 32 adjacent features of one batch row. Inputs are staged
// through a per-warp SMEM ring via cp.async (LDGSTS): completion is tracked
// by commit-groups, NOT the per-SM L1tex wavefront queue (~248 entries)
// that capped every LDG-based variant at ~64% of HBM. 128 stages in flight
// per warp (16KB) -> ~112KB/SM, 3.5x the LDG-path cap.
// Each thread consumes only the SMEM bytes its own cp.async wrote: no
// __syncthreads/__syncwarp needed, and the 128B-per-stage layout is
// bank-conflict-free.
__global__ void __launch_bounds__(BLOCK) alpha_filter_kernel(
    const float* __restrict__ in,     // [B, T, K]
    const float* __restrict__ init,   // [K]
    const float* __restrict__ tau,    // [K]
    float* __restrict__ out)          // [B, T, K]
{
    __shared__ float ring[NGROUPS][CHUNK][BLOCK];   // 16 KB

    const int lane = threadIdx.x;
    const int k    = blockIdx.x * BLOCK + lane;
    const int b    = blockIdx.y;

    // Per-feature coefficients (matches reference fp32 math)
    const float tc      = fmaxf(tau[k], 1e-8f);
    const float dt_tau  = 0.001f / tc;
    const float dt_tau2 = dt_tau / tc;
    const float e       = expf(-dt_tau);

    const float a00 = e * (1.0f - dt_tau);
    const float a01 = -e * dt_tau2;
    const float a10 = e * 0.001f;
    const float a11 = e * (1.0f + dt_tau);
    const float b0  = e * dt_tau2;
    const float b1  = 1.0f - a11;

    float x0 = 0.0f;
    float x1 = init[k];

    const size_t base = (size_t)b * T_STEPS * K_FEAT + (size_t)k;
    const float* ip = in  + base;
    float*       op = out + base;

    // Prologue: prefetch NGROUPS chunks (128 time steps) into the ring.
#pragma unroll
    for (int c = 0; c < NGROUPS; ++c) {
#pragma unroll
        for (int s = 0; s < CHUNK; ++s)
            __pipeline_memcpy_async(&ring[c][s][lane],
                                    ip + (size_t)(c * CHUNK + s) * K_FEAT, 4);
        __pipeline_commit();
    }

    // Main loop: wait for oldest group, consume its 16 steps, refill the
    // same slot with the chunk NGROUPS ahead, commit.
    int t = 0;
#pragma unroll 1
    for (int ci = 0; ci < NCHUNKS - NGROUPS; ++ci) {
        __pipeline_wait_prior(NGROUPS - 1);
        const int slot = ci & (NGROUPS - 1);

#pragma unroll
        for (int s = 0; s < CHUNK; ++s) {
            const float u   = ring[slot][s][lane];
            const float nx0 = fmaf(a00, x0, fmaf(a01, x1, b0 * u));
            const float nx1 = fmaf(a10, x0, fmaf(a11, x1, b1 * u));
            x0 = nx0;
            x1 = nx1;
            __stcs(op + (size_t)(t + s) * K_FEAT, nx1);
        }

        const float* gp = ip + (size_t)(ci + NGROUPS) * CHUNK * K_FEAT;
#pragma unroll
        for (int s = 0; s < CHUNK; ++s)
            __pipeline_memcpy_async(&ring[slot][s][lane],
                                    gp + (size_t)s * K_FEAT, 4);
        __pipeline_commit();

        t += CHUNK;
    }

    // Tail: drain the last NGROUPS groups (no further issues, so the
    // wait-prior bound shrinks with each chunk; immediates must be
    // compile-time constants).
#pragma unroll
    for (int j = 0; j < NGROUPS; ++j) {
        switch (j) {
            case 0: __pipeline_wait_prior(7); break;
            case 1: __pipeline_wait_prior(6); break;
            case 2: __pipeline_wait_prior(5); break;
            case 3: __pipeline_wait_prior(4); break;
            case 4: __pipeline_wait_prior(3); break;
            case 5: __pipeline_wait_prior(2); break;
            case 6: __pipeline_wait_prior(1); break;
            case 7: __pipeline_wait_prior(0); break;
        }
        const int slot = (NCHUNKS - NGROUPS + j) & (NGROUPS - 1);
#pragma unroll
        for (int s = 0; s < CHUNK; ++s) {
            const float u   = ring[slot][s][lane];
            const float nx0 = fmaf(a00, x0, fmaf(a01, x1, b0 * u));
            const float nx1 = fmaf(a10, x0, fmaf(a11, x1, b1 * u));
            x0 = nx0;
            x1 = nx1;
            __stcs(op + (size_t)(t + s) * K_FEAT, nx1);
        }
        t += CHUNK;
    }
}

extern "C" void kernel_launch(void* const* d_in, const int* in_sizes, int n_in,
                              void* d_out, int out_size) {
    const float* inputs = (const float*)d_in[0];   // [B, T, K]
    const float* init   = (const float*)d_in[1];   // [K]
    const float* tau    = (const float*)d_in[2];   // [K]
    float*       out    = (float*)d_out;

    const int batch = in_sizes[0] / (T_STEPS * K_FEAT);   // 64
    dim3 grid(K_FEAT / BLOCK, batch);                     // (16, 64) = 1024 CTAs
    alpha_filter_kernel<<<grid, BLOCK>>>(inputs, init, tau, out);
}

// round 12
// speedup vs baseline: 1.1199x; 1.1199x over previous
#include <cuda_runtime.h>
#include <math.h>

#define T_STEPS 1024
#define K_FEAT  512
#define BLOCK   64
#define PF      52   // prefetch depth, just under ~55 outstanding-LDG/warp HW cap

// One thread owns one (batch, feature) pair; serial 2-state affine scan over
// T=1024. Register ring of depth PF keeps 52 loads in flight/thread.
// R5 base (fastest measured: 42.1us kernel, 5.1 TB/s) with ONE change:
// __ldcg loads (L2-only, skip L1 allocation — zero-reuse stream makes L1
// caching pure overhead). Stores remain __stcs (evict-first, zero reuse).
// All other levers (MLP depth, vector width, cp.async staging, wave
// balance) tested and falsified as the bind; ~5.1 TB/s appears to be the
// chip's mixed 50/50 R/W stream ceiling.
// (Resubmission of R9 — that round died to a broker/container failure,
// which is infra, not kernel; no measurement was produced.)
__global__ void __launch_bounds__(BLOCK) alpha_filter_kernel(
    const float* __restrict__ in,     // [B, T, K]
    const float* __restrict__ init,   // [K]
    const float* __restrict__ tau,    // [K]
    float* __restrict__ out)          // [B, T, K]
{
    const int k = blockIdx.x * BLOCK + threadIdx.x;
    const int b = blockIdx.y;

    // Per-feature coefficients (matches reference fp32 math)
    const float tc      = fmaxf(tau[k], 1e-8f);
    const float dt_tau  = 0.001f / tc;
    const float dt_tau2 = dt_tau / tc;
    const float e       = expf(-dt_tau);

    const float a00 = e * (1.0f - dt_tau);
    const float a01 = -e * dt_tau2;
    const float a10 = e * 0.001f;
    const float a11 = e * (1.0f + dt_tau);
    const float b0  = e * dt_tau2;
    const float b1  = 1.0f - a11;

    float x0 = 0.0f;
    float x1 = init[k];

    const size_t base = (size_t)b * T_STEPS * K_FEAT + (size_t)k;
    const float* ip = in  + base;
    float*       op = out + base;

    // Prologue: fill the prefetch ring with t = 0..PF-1
    float buf[PF];
#pragma unroll
    for (int i = 0; i < PF; ++i)
        buf[i] = __ldcg(ip + (size_t)i * K_FEAT);
    ip += (size_t)PF * K_FEAT;

    // Main loop: consume step t, prefetch step t+PF.
    // Steps that still prefetch = T_STEPS - PF = 972: 18 full chunks of 52
    // plus a partial chunk of 36.
#pragma unroll 1
    for (int done = 0; done + PF <= T_STEPS - PF; done += PF) {
#pragma unroll
        for (int i = 0; i < PF; ++i) {
            const float u = buf[i];
            buf[i] = __ldcg(ip + (size_t)i * K_FEAT);   // prefetch t + PF
            const float nx0 = fmaf(a00, x0, fmaf(a01, x1, b0 * u));
            const float nx1 = fmaf(a10, x0, fmaf(a11, x1, b1 * u));
            x0 = nx0;
            x1 = nx1;
            __stcs(op + (size_t)i * K_FEAT, nx1);
        }
        ip += (size_t)PF * K_FEAT;
        op += (size_t)PF * K_FEAT;
    }

    // Partial chunk: remaining steps that still prefetch.
#define REM ((T_STEPS - PF) % PF)
#if REM
#pragma unroll
    for (int i = 0; i < REM; ++i) {
        const float u = buf[i];
        buf[i] = __ldcg(ip + (size_t)i * K_FEAT);
        const float nx0 = fmaf(a00, x0, fmaf(a01, x1, b0 * u));
        const float nx1 = fmaf(a10, x0, fmaf(a11, x1, b1 * u));
        x0 = nx0;
        x1 = nx1;
        __stcs(op + (size_t)i * K_FEAT, nx1);
    }
    ip += (size_t)REM * K_FEAT;
    op += (size_t)REM * K_FEAT;
#endif

    // Epilogue: drain the last PF buffered inputs (no further prefetch).
    // Ring read order continues from index REM (mod PF).
#pragma unroll
    for (int i = 0; i < PF; ++i) {
        const int idx = (REM + i) % PF;
        const float u = buf[idx];
        const float nx0 = fmaf(a00, x0, fmaf(a01, x1, b0 * u));
        const float nx1 = fmaf(a10, x0, fmaf(a11, x1, b1 * u));
        x0 = nx0;
        x1 = nx1;
        __stcs(op + (size_t)i * K_FEAT, nx1);
    }
}

extern "C" void kernel_launch(void* const* d_in, const int* in_sizes, int n_in,
                              void* d_out, int out_size) {
    const float* inputs = (const float*)d_in[0];   // [B, T, K]
    const float* init   = (const float*)d_in[1];   // [K]
    const float* tau    = (const float*)d_in[2];   // [K]
    float*       out    = (float*)d_out;

    const int batch = in_sizes[0] / (T_STEPS * K_FEAT);   // 64
    dim3 grid(K_FEAT / BLOCK, batch);
    alpha_filter_kernel<<<grid, BLOCK>>>(inputs, init, tau, out);
}

// round 13
// speedup vs baseline: 1.1575x; 1.0336x over previous
#include <cuda_runtime.h>
#include <math.h>

#define T_STEPS 1024
#define K_FEAT  512
#define BLOCK   64
#define PF      52   // prefetch depth, just under ~55 outstanding-LDG/warp HW cap

// One thread owns one (batch, feature) pair; serial 2-state affine scan over
// T=1024. Register ring of depth PF keeps 52 loads in flight/thread.
// R5 base (best measured: 42.1us kernel, 5.1 TB/s) with ONE change:
// __stwt stores (write-through, no L2 write-allocate) — probes whether the
// write stream's LTS slot/tag occupancy is what holds the read stream at
// ~64% of HBM. Loads stay default-cached (R11 falsified __ldcg: default L1
// caching on the read stream is better).
// Policy tally so far: ld-default+stcs (42.1) > ld-default+plain (42.9)
// > ldcg+stcs (43.8) > ldcs+stcs (45.5).
__global__ void __launch_bounds__(BLOCK) alpha_filter_kernel(
    const float* __restrict__ in,     // [B, T, K]
    const float* __restrict__ init,   // [K]
    const float* __restrict__ tau,    // [K]
    float* __restrict__ out)          // [B, T, K]
{
    const int k = blockIdx.x * BLOCK + threadIdx.x;
    const int b = blockIdx.y;

    // Per-feature coefficients (matches reference fp32 math)
    const float tc      = fmaxf(tau[k], 1e-8f);
    const float dt_tau  = 0.001f / tc;
    const float dt_tau2 = dt_tau / tc;
    const float e       = expf(-dt_tau);

    const float a00 = e * (1.0f - dt_tau);
    const float a01 = -e * dt_tau2;
    const float a10 = e * 0.001f;
    const float a11 = e * (1.0f + dt_tau);
    const float b0  = e * dt_tau2;
    const float b1  = 1.0f - a11;

    float x0 = 0.0f;
    float x1 = init[k];

    const size_t base = (size_t)b * T_STEPS * K_FEAT + (size_t)k;
    const float* ip = in  + base;
    float*       op = out + base;

    // Prologue: fill the prefetch ring with t = 0..PF-1
    float buf[PF];
#pragma unroll
    for (int i = 0; i < PF; ++i)
        buf[i] = ip[(size_t)i * K_FEAT];
    ip += (size_t)PF * K_FEAT;

    // Main loop: consume step t, prefetch step t+PF.
    // Steps that still prefetch = T_STEPS - PF = 972: 18 full chunks of 52
    // plus a partial chunk of 36.
#pragma unroll 1
    for (int done = 0; done + PF <= T_STEPS - PF; done += PF) {
#pragma unroll
        for (int i = 0; i < PF; ++i) {
            const float u = buf[i];
            buf[i] = ip[(size_t)i * K_FEAT];   // prefetch t + PF
            const float nx0 = fmaf(a00, x0, fmaf(a01, x1, b0 * u));
            const float nx1 = fmaf(a10, x0, fmaf(a11, x1, b1 * u));
            x0 = nx0;
            x1 = nx1;
            __stwt(op + (size_t)i * K_FEAT, nx1);
        }
        ip += (size_t)PF * K_FEAT;
        op += (size_t)PF * K_FEAT;
    }

    // Partial chunk: remaining steps that still prefetch.
#define REM ((T_STEPS - PF) % PF)
#if REM
#pragma unroll
    for (int i = 0; i < REM; ++i) {
        const float u = buf[i];
        buf[i] = ip[(size_t)i * K_FEAT];
        const float nx0 = fmaf(a00, x0, fmaf(a01, x1, b0 * u));
        const float nx1 = fmaf(a10, x0, fmaf(a11, x1, b1 * u));
        x0 = nx0;
        x1 = nx1;
        __stwt(op + (size_t)i * K_FEAT, nx1);
    }
    ip += (size_t)REM * K_FEAT;
    op += (size_t)REM * K_FEAT;
#endif

    // Epilogue: drain the last PF buffered inputs (no further prefetch).
    // Ring read order continues from index REM (mod PF).
#pragma unroll
    for (int i = 0; i < PF; ++i) {
        const int idx = (REM + i) % PF;
        const float u = buf[idx];
        const float nx0 = fmaf(a00, x0, fmaf(a01, x1, b0 * u));
        const float nx1 = fmaf(a10, x0, fmaf(a11, x1, b1 * u));
        x0 = nx0;
        x1 = nx1;
        __stwt(op + (size_t)i * K_FEAT, nx1);
    }
}

extern "C" void kernel_launch(void* const* d_in, const int* in_sizes, int n_in,
                              void* d_out, int out_size) {
    const float* inputs = (const float*)d_in[0];   // [B, T, K]
    const float* init   = (const float*)d_in[1];   // [K]
    const float* tau    = (const float*)d_in[2];   // [K]
    float*       out    = (float*)d_out;

    const int batch = in_sizes[0] / (T_STEPS * K_FEAT);   // 64
    dim3 grid(K_FEAT / BLOCK, batch);
    alpha_filter_kernel<<<grid, BLOCK>>>(inputs, init, tau, out);
}